// round 13
// baseline (speedup 1.0000x reference)
#include <cuda_runtime.h>
#include <cuda_fp16.h>
#include <cstdint>

// out[T,N] = (x[T,K] @ W[N,K]^T) * scales[N] + bias[N];  T=8192, N=4096, K=4096
//
// R12: fp16 HMMA, CTA 128x256, 8 warps (64x64), BK=64, 4 stages treated as
// 2 PAIRS: one wait+sync per 2 k-chunks (32 edges instead of 64), 8
// straight-line ks-phases per edge with fragment double-buffering and
// per-SMSP phase rotation. Fills spread 1/8 per phase into the other pair.

#define T_DIM 8192
#define N_DIM 4096
#define K_DIM 4096

#define BM 128
#define BN 256
#define BK 64
#define THREADS 256
#define NPAIR (K_DIM / (2 * BK))   // 32

#define A_B 0
#define B_B 16384
#define STAGE_B 49152
#define SMEM_TOTAL (4 * STAGE_B)   // 196608

#define SWZ(o) ((o) ^ (((o) >> 3) & 0x70))

__device__ __align__(16) __half g_x[(size_t)T_DIM * K_DIM];
__device__ __align__(16) __half g_w[(size_t)N_DIM * K_DIM];

// ---------------- asm helpers ----------------
__device__ __forceinline__ uint32_t smem_u32(const void* p) {
    uint32_t a;
    asm("{ .reg .u64 t; cvta.to.shared.u64 t, %1; cvt.u32.u64 %0, t; }" : "=r"(a) : "l"(p));
    return a;
}
__device__ __forceinline__ void cp16(uint32_t dst, const void* src) {
    asm volatile("cp.async.cg.shared.global [%0], [%1], 16;" :: "r"(dst), "l"(src));
}
__device__ __forceinline__ void cp_commit() {
    asm volatile("cp.async.commit_group;" ::: "memory");
}
__device__ __forceinline__ void cp_wait0() {
    asm volatile("cp.async.wait_group 0;" ::: "memory");
}
__device__ __forceinline__ void ldm4(uint32_t& r0, uint32_t& r1, uint32_t& r2, uint32_t& r3,
                                     uint32_t addr) {
    asm volatile("ldmatrix.sync.aligned.m8n8.x4.shared.b16 {%0,%1,%2,%3}, [%4];"
                 : "=r"(r0), "=r"(r1), "=r"(r2), "=r"(r3) : "r"(addr));
}
__device__ __forceinline__ void mma_f16(float* d, uint32_t a0, uint32_t a1, uint32_t a2,
                                        uint32_t a3, uint32_t b0, uint32_t b1) {
    asm volatile(
        "mma.sync.aligned.m16n8k16.row.col.f32.f16.f16.f32 "
        "{%0,%1,%2,%3}, {%4,%5,%6,%7}, {%8,%9}, {%0,%1,%2,%3};"
        : "+f"(d[0]), "+f"(d[1]), "+f"(d[2]), "+f"(d[3])
        : "r"(a0), "r"(a1), "r"(a2), "r"(a3), "r"(b0), "r"(b1));
}

// ---------------- merged prepass ----------------
#define XBLKS (T_DIM * K_DIM / 4 / 256)     // 32768
#define WBLKS (N_DIM * K_DIM / 4 / 256)     // 16384

__global__ void __launch_bounds__(256)
convert_all_kernel(const float4* __restrict__ X4, const int4* __restrict__ W4)
{
    int b = blockIdx.x;
    if (b < XBLKS) {
        int i = b * 256 + threadIdx.x;
        float4 v = X4[i];
        __half2 h0 = __floats2half2_rn(v.x, v.y);
        __half2 h1 = __floats2half2_rn(v.z, v.w);
        uint2 u;
        u.x = *reinterpret_cast<uint32_t*>(&h0);
        u.y = *reinterpret_cast<uint32_t*>(&h1);
        *reinterpret_cast<uint2*>(g_x + (size_t)i * 4) = u;
    } else {
        int i = (b - XBLKS) * 256 + threadIdx.x;
        int4 v = W4[i];
        __half2 h0 = __floats2half2_rn((float)v.x, (float)v.y);
        __half2 h1 = __floats2half2_rn((float)v.z, (float)v.w);
        uint2 u;
        u.x = *reinterpret_cast<uint32_t*>(&h0);
        u.y = *reinterpret_cast<uint32_t*>(&h1);
        *reinterpret_cast<uint2*>(g_w + (size_t)i * 4) = u;
    }
}

// ---------------- main GEMM ----------------
__device__ __forceinline__ void fill_quarter(uint32_t base, int m0, int n0, int kk,
                                             int tid, int q) {
    {
        int i = tid + q * 256;
        int r = i >> 3, c = i & 7;
        cp16(base + A_B + SWZ((uint32_t)((r << 7) + (c << 4))),
             g_x + (size_t)(m0 + r) * K_DIM + kk + c * 8);
    }
    #pragma unroll
    for (int jj = 0; jj < 2; jj++) {
        int i = tid + (q * 2 + jj) * 256;
        int r = i >> 3, c = i & 7;
        cp16(base + B_B + SWZ((uint32_t)((r << 7) + (c << 4))),
             g_w + (size_t)(n0 + r) * K_DIM + kk + c * 8);
    }
}

__global__ void __launch_bounds__(THREADS, 1)
qlinear_hmma_kernel(const float* __restrict__ scales,
                    const float* __restrict__ bias,
                    float* __restrict__ Out)
{
    extern __shared__ char smem[];
    const uint32_t sb = smem_u32(smem);
    const int tid = threadIdx.x;
    const int wid = tid >> 5;
    const int lane = tid & 31;

    const int n0 = blockIdx.x * BN;
    const int m0 = blockIdx.y * BM;

    const int wm = wid & 1;        // 2 warps over M
    const int wn = wid >> 1;       // 4 warps over N

    const int frow = lane & 15;
    const int fcol = lane >> 4;
    uint32_t aoff[4], boff[4];
    #pragma unroll
    for (int mt = 0; mt < 4; mt++) {
        uint32_t row = (uint32_t)(wm * 64 + mt * 16 + frow);
        aoff[mt] = A_B + ((row << 7) ^ ((row & 7) << 4));
    }
    #pragma unroll
    for (int nt = 0; nt < 4; nt++) {
        uint32_t row = (uint32_t)(wn * 64 + nt * 16 + frow);
        boff[nt] = B_B + ((row << 7) ^ ((row & 7) << 4));
    }
    const uint32_t kbase = (uint32_t)(fcol << 4);

    // SMSP de-phasing: warps sharing an SMSP (wid, wid+4) offset by 2 phases
    const int rot = (wid >> 2) * 2;

    float acc[4][8][4];
    #pragma unroll
    for (int mt = 0; mt < 4; mt++)
        #pragma unroll
        for (int nf = 0; nf < 8; nf++)
            #pragma unroll
            for (int q = 0; q < 4; q++) acc[mt][nf][q] = 0.0f;

    // prologue: fill pair0 = stages {0,1} with chunks 0,1
    #pragma unroll
    for (int q = 0; q < 4; q++) fill_quarter(sb,           m0, n0, 0,  tid, q);
    #pragma unroll
    for (int q = 0; q < 4; q++) fill_quarter(sb + STAGE_B, m0, n0, BK, tid, q);
    cp_commit();

    for (int p = 0; p < NPAIR; p++) {
        cp_wait0();               // pair (p&1) fills complete (committed last iter)
        __syncthreads();          // all warps done reading the other pair

        const uint32_t cbase = sb + (uint32_t)((p & 1) * (2 * STAGE_B));
        const uint32_t pbase = sb + (uint32_t)(((p & 1) ^ 1) * (2 * STAGE_B));
        const bool do_fill = (p + 1 < NPAIR);
        const int kk0 = (p + 1) * 2 * BK;

        // fragment double buffers
        uint32_t bf[2][8][2];
        uint32_t a0b[2][4];

        // preload phase 0 (hh = rot)
        {
            const uint32_t b0 = cbase + (uint32_t)((rot >> 2) * STAGE_B);
            const uint32_t kp = kbase + (uint32_t)((rot & 3) * 32);
            #pragma unroll
            for (int nt = 0; nt < 4; nt++) {
                uint32_t r0, r1, r2, r3;
                ldm4(r0, r1, r2, r3, b0 + (boff[nt] ^ kp));
                bf[0][nt * 2 + 0][0] = r0; bf[0][nt * 2 + 0][1] = r2;
                bf[0][nt * 2 + 1][0] = r1; bf[0][nt * 2 + 1][1] = r3;
            }
            ldm4(a0b[0][0], a0b[0][1], a0b[0][2], a0b[0][3], b0 + (aoff[0] ^ kp));
        }

        #pragma unroll
        for (int h = 0; h < 8; h++) {
            const int hh = (h + rot) & 7;
            const uint32_t bcur = cbase + (uint32_t)((hh >> 2) * STAGE_B);
            const uint32_t kpart = kbase + (uint32_t)((hh & 3) * 32);
            const int cur = h & 1, nxt = cur ^ 1;

            if (do_fill)
                fill_quarter(pbase + (uint32_t)((h >> 2) * STAGE_B),
                             m0, n0, kk0 + (h >> 2) * BK, tid, h & 3);

            if (h < 7) {
                const int hn = (h + 1 + rot) & 7;
                const uint32_t bn = cbase + (uint32_t)((hn >> 2) * STAGE_B);
                const uint32_t kn = kbase + (uint32_t)((hn & 3) * 32);
                #pragma unroll
                for (int nt = 0; nt < 4; nt++) {
                    uint32_t r0, r1, r2, r3;
                    ldm4(r0, r1, r2, r3, bn + (boff[nt] ^ kn));
                    bf[nxt][nt * 2 + 0][0] = r0; bf[nxt][nt * 2 + 0][1] = r2;
                    bf[nxt][nt * 2 + 1][0] = r1; bf[nxt][nt * 2 + 1][1] = r3;
                }
                ldm4(a0b[nxt][0], a0b[nxt][1], a0b[nxt][2], a0b[nxt][3],
                     bn + (aoff[0] ^ kn));
            }

            #pragma unroll
            for (int mt = 0; mt < 4; mt++) {
                uint32_t a0, a1, a2, a3;
                if (mt == 0) {
                    a0 = a0b[cur][0]; a1 = a0b[cur][1];
                    a2 = a0b[cur][2]; a3 = a0b[cur][3];
                } else {
                    ldm4(a0, a1, a2, a3, bcur + (aoff[mt] ^ kpart));
                }
                #pragma unroll
                for (int nf = 0; nf < 8; nf++)
                    mma_f16(acc[mt][nf], a0, a1, a2, a3,
                            bf[cur][nf][0], bf[cur][nf][1]);
            }
        }
        cp_commit();              // one group per pair (possibly empty)
    }
    cp_wait0();

    // ---- epilogue ----
    #pragma unroll
    for (int mt = 0; mt < 4; mt++) {
        const int mrow = m0 + wm * 64 + mt * 16 + (lane >> 2);
        #pragma unroll
        for (int nf = 0; nf < 8; nf++) {
            const int n = n0 + wn * 64 + nf * 8 + (lane & 3) * 2;
            float2 sc = *reinterpret_cast<const float2*>(scales + n);
            float2 bi = *reinterpret_cast<const float2*>(bias + n);
            float2 o0, o1;
            o0.x = acc[mt][nf][0] * sc.x + bi.x;
            o0.y = acc[mt][nf][1] * sc.y + bi.y;
            o1.x = acc[mt][nf][2] * sc.x + bi.x;
            o1.y = acc[mt][nf][3] * sc.y + bi.y;
            *reinterpret_cast<float2*>(Out + (size_t)mrow * N_DIM + n) = o0;
            *reinterpret_cast<float2*>(Out + (size_t)(mrow + 8) * N_DIM + n) = o1;
        }
    }
}

// ---------------- host ----------------
extern "C" void kernel_launch(void* const* d_in, const int* in_sizes, int n_in,
                              void* d_out, int out_size)
{
    const float* x      = (const float*)d_in[0];
    const int*   w      = (const int*)d_in[1];
    const float* scales = (const float*)d_in[2];
    const float* bias   = (const float*)d_in[3];
    float* out = (float*)d_out;

    cudaFuncSetAttribute(qlinear_hmma_kernel,
                         cudaFuncAttributeMaxDynamicSharedMemorySize, SMEM_TOTAL);

    convert_all_kernel<<<XBLKS + WBLKS, 256>>>((const float4*)x, (const int4*)w);

    dim3 grid(N_DIM / BN, T_DIM / BM);   // 16 x 64
    qlinear_hmma_kernel<<<grid, THREADS, SMEM_TOTAL>>>(scales, bias, out);
}

// round 14
// speedup vs baseline: 1.0688x; 1.0688x over previous
#include <cuda_runtime.h>
#include <cuda_fp16.h>
#include <cstdint>

// out[T,N] = (x[T,K] @ W[N,K]^T) * scales[N] + bias[N];  T=8192, N=4096, K=4096
//
// R13: R11 base (fp16 HMMA, CTA 128x256, 8 warps 64x64, BK=64, 4-stage
// cp.async wait_group 2, quarter-fills, B-frag + A(mt0) double buffering,
// SMSP de-phasing) with INCREMENTAL FILL ADDRESSING:
//   per-thread swizzled smem offset + global base pointers precomputed once;
//   quarters advance by +32 rows (src += 32*K, dst += 4096 — swizzle bits
//   unchanged), k-chunks advance src by += BK. Kills the per-iter IMAD.WIDE
//   chains that were ~18% of issue.

#define T_DIM 8192
#define N_DIM 4096
#define K_DIM 4096

#define BM 128
#define BN 256
#define BK 64
#define STAGES 4
#define THREADS 256
#define KITERS (K_DIM / BK)      // 64

#define A_B 0
#define B_B 16384
#define STAGE_B 49152
#define SMEM_TOTAL (STAGES * STAGE_B)   // 196608

#define SWZ(o) ((o) ^ (((o) >> 3) & 0x70))

// row stride per quarter-step: 32 rows
#define QSTRIDE (32 * K_DIM)            // in __half elements
#define DST_QSTRIDE 4096                // 32 rows * 128B

__device__ __align__(16) __half g_x[(size_t)T_DIM * K_DIM];
__device__ __align__(16) __half g_w[(size_t)N_DIM * K_DIM];

// ---------------- asm helpers ----------------
__device__ __forceinline__ uint32_t smem_u32(const void* p) {
    uint32_t a;
    asm("{ .reg .u64 t; cvta.to.shared.u64 t, %1; cvt.u32.u64 %0, t; }" : "=r"(a) : "l"(p));
    return a;
}
__device__ __forceinline__ void cp16(uint32_t dst, const void* src) {
    asm volatile("cp.async.cg.shared.global [%0], [%1], 16;" :: "r"(dst), "l"(src));
}
__device__ __forceinline__ void cp_commit() {
    asm volatile("cp.async.commit_group;" ::: "memory");
}
__device__ __forceinline__ void cp_wait2() {
    asm volatile("cp.async.wait_group 2;" ::: "memory");
}
__device__ __forceinline__ void cp_wait0() {
    asm volatile("cp.async.wait_group 0;" ::: "memory");
}
__device__ __forceinline__ void ldm4(uint32_t& r0, uint32_t& r1, uint32_t& r2, uint32_t& r3,
                                     uint32_t addr) {
    asm volatile("ldmatrix.sync.aligned.m8n8.x4.shared.b16 {%0,%1,%2,%3}, [%4];"
                 : "=r"(r0), "=r"(r1), "=r"(r2), "=r"(r3) : "r"(addr));
}
__device__ __forceinline__ void mma_f16(float* d, uint32_t a0, uint32_t a1, uint32_t a2,
                                        uint32_t a3, uint32_t b0, uint32_t b1) {
    asm volatile(
        "mma.sync.aligned.m16n8k16.row.col.f32.f16.f16.f32 "
        "{%0,%1,%2,%3}, {%4,%5,%6,%7}, {%8,%9}, {%0,%1,%2,%3};"
        : "+f"(d[0]), "+f"(d[1]), "+f"(d[2]), "+f"(d[3])
        : "r"(a0), "r"(a1), "r"(a2), "r"(a3), "r"(b0), "r"(b1));
}

// ---------------- merged prepass ----------------
#define XBLKS (T_DIM * K_DIM / 4 / 256)     // 32768
#define WBLKS (N_DIM * K_DIM / 4 / 256)     // 16384

__global__ void __launch_bounds__(256)
convert_all_kernel(const float4* __restrict__ X4, const int4* __restrict__ W4)
{
    int b = blockIdx.x;
    if (b < XBLKS) {
        int i = b * 256 + threadIdx.x;
        float4 v = X4[i];
        __half2 h0 = __floats2half2_rn(v.x, v.y);
        __half2 h1 = __floats2half2_rn(v.z, v.w);
        uint2 u;
        u.x = *reinterpret_cast<uint32_t*>(&h0);
        u.y = *reinterpret_cast<uint32_t*>(&h1);
        *reinterpret_cast<uint2*>(g_x + (size_t)i * 4) = u;
    } else {
        int i = (b - XBLKS) * 256 + threadIdx.x;
        int4 v = W4[i];
        __half2 h0 = __floats2half2_rn((float)v.x, (float)v.y);
        __half2 h1 = __floats2half2_rn((float)v.z, (float)v.w);
        uint2 u;
        u.x = *reinterpret_cast<uint32_t*>(&h0);
        u.y = *reinterpret_cast<uint32_t*>(&h1);
        *reinterpret_cast<uint2*>(g_w + (size_t)i * 4) = u;
    }
}

// ---------------- main GEMM ----------------
// incremental quarter fill: dst/src advance by fixed strides; q in [0,4)
__device__ __forceinline__ void fill_quarter_inc(uint32_t dstA, uint32_t dstB,
                                                 const __half* srcA,
                                                 const __half* srcB, int q) {
    cp16(dstA + (uint32_t)(q * DST_QSTRIDE), srcA + (size_t)q * QSTRIDE);
    cp16(dstB + (uint32_t)((q * 2 + 0) * DST_QSTRIDE), srcB + (size_t)(q * 2 + 0) * QSTRIDE);
    cp16(dstB + (uint32_t)((q * 2 + 1) * DST_QSTRIDE), srcB + (size_t)(q * 2 + 1) * QSTRIDE);
}

__global__ void __launch_bounds__(THREADS, 1)
qlinear_hmma_kernel(const float* __restrict__ scales,
                    const float* __restrict__ bias,
                    float* __restrict__ Out)
{
    extern __shared__ char smem[];
    const uint32_t sb = smem_u32(smem);
    const int tid = threadIdx.x;
    const int wid = tid >> 5;
    const int lane = tid & 31;

    const int n0 = blockIdx.x * BN;
    const int m0 = blockIdx.y * BM;

    const int wm = wid & 1;        // 2 warps over M
    const int wn = wid >> 1;       // 4 warps over N

    // per-thread fill bases (row = tid>>3 in [0,32), chunk = tid&7)
    const int fr = tid >> 3;
    const int fc = tid & 7;
    const uint32_t swz_t = SWZ((uint32_t)((fr << 7) + (fc << 4)));
    const __half* srcA = g_x + (size_t)(m0 + fr) * K_DIM + fc * 8;
    const __half* srcB = g_w + (size_t)(n0 + fr) * K_DIM + fc * 8;

    const int frow = lane & 15;
    const int fcol = lane >> 4;
    uint32_t aoff[4], boff[4];
    #pragma unroll
    for (int mt = 0; mt < 4; mt++) {
        uint32_t row = (uint32_t)(wm * 64 + mt * 16 + frow);
        aoff[mt] = A_B + ((row << 7) ^ ((row & 7) << 4));
    }
    #pragma unroll
    for (int nt = 0; nt < 4; nt++) {
        uint32_t row = (uint32_t)(wn * 64 + nt * 16 + frow);
        boff[nt] = B_B + ((row << 7) ^ ((row & 7) << 4));
    }
    const uint32_t kbase = (uint32_t)(fcol << 4);

    // SMSP de-phasing: warps sharing an SMSP (wid, wid+4) offset by 2 phases
    const int rot = (wid >> 2) * 2;

    float acc[4][8][4];
    #pragma unroll
    for (int mt = 0; mt < 4; mt++)
        #pragma unroll
        for (int nf = 0; nf < 8; nf++)
            #pragma unroll
            for (int q = 0; q < 4; q++) acc[mt][nf][q] = 0.0f;

    // prologue: fill stages 0,1,2 with chunks 0,1,2
    #pragma unroll
    for (int s = 0; s < 3; s++) {
        const uint32_t dA = sb + s * STAGE_B + A_B + swz_t;
        const uint32_t dB = sb + s * STAGE_B + B_B + swz_t;
        #pragma unroll
        for (int q = 0; q < 4; q++)
            fill_quarter_inc(dA, dB, srcA + s * BK, srcB + s * BK, q);
        cp_commit();
    }
    srcA += 3 * BK;               // next fill chunk = 3
    srcB += 3 * BK;

    int cons = 0, prod = 3;
    for (int c = 0; c < KITERS; c++) {
        cp_wait2();
        __syncthreads();

        const uint32_t base = sb + cons * STAGE_B;
        const bool do_fill = (c + 3 < KITERS);
        const uint32_t dA = sb + prod * STAGE_B + A_B + swz_t;
        const uint32_t dB = sb + prod * STAGE_B + B_B + swz_t;

        // double-buffered fragments: B (8 frags) + A(mt0) for the next phase
        uint32_t bf[2][8][2];
        uint32_t a0b[2][4];

        // preload phase j=0 (ks = rot)
        {
            const uint32_t kpart = kbase + (uint32_t)(rot * 32);
            #pragma unroll
            for (int nt = 0; nt < 4; nt++) {
                uint32_t r0, r1, r2, r3;
                ldm4(r0, r1, r2, r3, base + (boff[nt] ^ kpart));
                bf[0][nt * 2 + 0][0] = r0; bf[0][nt * 2 + 0][1] = r2;
                bf[0][nt * 2 + 1][0] = r1; bf[0][nt * 2 + 1][1] = r3;
            }
            ldm4(a0b[0][0], a0b[0][1], a0b[0][2], a0b[0][3],
                 base + (aoff[0] ^ kpart));
        }

        #pragma unroll
        for (int j = 0; j < 4; j++) {
            const int ks = (j + rot) & 3;
            const int cur = j & 1, nxt = cur ^ 1;
            const uint32_t kpart = kbase + (uint32_t)(ks * 32);

            if (do_fill)
                fill_quarter_inc(dA, dB, srcA, srcB, j);

            // prefetch next phase's fragments before this phase's MMAs
            if (j < 3) {
                const uint32_t kn = kbase + (uint32_t)((((j + 1 + rot) & 3)) * 32);
                #pragma unroll
                for (int nt = 0; nt < 4; nt++) {
                    uint32_t r0, r1, r2, r3;
                    ldm4(r0, r1, r2, r3, base + (boff[nt] ^ kn));
                    bf[nxt][nt * 2 + 0][0] = r0; bf[nxt][nt * 2 + 0][1] = r2;
                    bf[nxt][nt * 2 + 1][0] = r1; bf[nxt][nt * 2 + 1][1] = r3;
                }
                ldm4(a0b[nxt][0], a0b[nxt][1], a0b[nxt][2], a0b[nxt][3],
                     base + (aoff[0] ^ kn));
            }

            #pragma unroll
            for (int mt = 0; mt < 4; mt++) {
                uint32_t a0, a1, a2, a3;
                if (mt == 0) {
                    a0 = a0b[cur][0]; a1 = a0b[cur][1];
                    a2 = a0b[cur][2]; a3 = a0b[cur][3];
                } else {
                    ldm4(a0, a1, a2, a3, base + (aoff[mt] ^ kpart));
                }
                #pragma unroll
                for (int nf = 0; nf < 8; nf++)
                    mma_f16(acc[mt][nf], a0, a1, a2, a3,
                            bf[cur][nf][0], bf[cur][nf][1]);
            }
        }
        cp_commit();
        srcA += BK;               // next fill chunk
        srcB += BK;

        cons = (cons == STAGES - 1) ? 0 : cons + 1;
        prod = (prod == STAGES - 1) ? 0 : prod + 1;
    }
    cp_wait0();

    // ---- epilogue ----
    #pragma unroll
    for (int mt = 0; mt < 4; mt++) {
        const int mrow = m0 + wm * 64 + mt * 16 + (lane >> 2);
        #pragma unroll
        for (int nf = 0; nf < 8; nf++) {
            const int n = n0 + wn * 64 + nf * 8 + (lane & 3) * 2;
            float2 sc = *reinterpret_cast<const float2*>(scales + n);
            float2 bi = *reinterpret_cast<const float2*>(bias + n);
            float2 o0, o1;
            o0.x = acc[mt][nf][0] * sc.x + bi.x;
            o0.y = acc[mt][nf][1] * sc.y + bi.y;
            o1.x = acc[mt][nf][2] * sc.x + bi.x;
            o1.y = acc[mt][nf][3] * sc.y + bi.y;
            *reinterpret_cast<float2*>(Out + (size_t)mrow * N_DIM + n) = o0;
            *reinterpret_cast<float2*>(Out + (size_t)(mrow + 8) * N_DIM + n) = o1;
        }
    }
}

// ---------------- host ----------------
extern "C" void kernel_launch(void* const* d_in, const int* in_sizes, int n_in,
                              void* d_out, int out_size)
{
    const float* x      = (const float*)d_in[0];
    const int*   w      = (const int*)d_in[1];
    const float* scales = (const float*)d_in[2];
    const float* bias   = (const float*)d_in[3];
    float* out = (float*)d_out;

    cudaFuncSetAttribute(qlinear_hmma_kernel,
                         cudaFuncAttributeMaxDynamicSharedMemorySize, SMEM_TOTAL);

    convert_all_kernel<<<XBLKS + WBLKS, 256>>>((const float4*)x, (const int4*)w);

    dim3 grid(N_DIM / BN, T_DIM / BM);   // 16 x 64
    qlinear_hmma_kernel<<<grid, THREADS, SMEM_TOTAL>>>(scales, bias, out);
}

// round 15
// speedup vs baseline: 1.0922x; 1.0218x over previous
#include <cuda_runtime.h>
#include <cuda_fp16.h>
#include <cstdint>

// out[T,N] = (x[T,K] @ W[N,K]^T) * scales[N] + bias[N];  T=8192, N=4096, K=4096
//
// R14: R13 base (fp16 HMMA, CTA 128x256, 8 warps 64x64, BK=64, 4-stage
// cp.async wait_group 2, incremental fill addressing, SMSP de-phasing) with
// FULL fragment double buffering: each ks-phase issues ALL 8 ldmatrix ops
// (4 A + 4 B) for the NEXT phase before its own 32 MMAs, so fragment loads
// always have a full MMA block (~256 issue cyc) of cover.

#define T_DIM 8192
#define N_DIM 4096
#define K_DIM 4096

#define BM 128
#define BN 256
#define BK 64
#define STAGES 4
#define THREADS 256
#define KITERS (K_DIM / BK)      // 64

#define A_B 0
#define B_B 16384
#define STAGE_B 49152
#define SMEM_TOTAL (STAGES * STAGE_B)   // 196608

#define SWZ(o) ((o) ^ (((o) >> 3) & 0x70))

#define QSTRIDE (32 * K_DIM)            // 32 rows, in __half elements
#define DST_QSTRIDE 4096                // 32 rows * 128B

__device__ __align__(16) __half g_x[(size_t)T_DIM * K_DIM];
__device__ __align__(16) __half g_w[(size_t)N_DIM * K_DIM];

// ---------------- asm helpers ----------------
__device__ __forceinline__ uint32_t smem_u32(const void* p) {
    uint32_t a;
    asm("{ .reg .u64 t; cvta.to.shared.u64 t, %1; cvt.u32.u64 %0, t; }" : "=r"(a) : "l"(p));
    return a;
}
__device__ __forceinline__ void cp16(uint32_t dst, const void* src) {
    asm volatile("cp.async.cg.shared.global [%0], [%1], 16;" :: "r"(dst), "l"(src));
}
__device__ __forceinline__ void cp_commit() {
    asm volatile("cp.async.commit_group;" ::: "memory");
}
__device__ __forceinline__ void cp_wait2() {
    asm volatile("cp.async.wait_group 2;" ::: "memory");
}
__device__ __forceinline__ void cp_wait0() {
    asm volatile("cp.async.wait_group 0;" ::: "memory");
}
__device__ __forceinline__ void ldm4(uint32_t& r0, uint32_t& r1, uint32_t& r2, uint32_t& r3,
                                     uint32_t addr) {
    asm volatile("ldmatrix.sync.aligned.m8n8.x4.shared.b16 {%0,%1,%2,%3}, [%4];"
                 : "=r"(r0), "=r"(r1), "=r"(r2), "=r"(r3) : "r"(addr));
}
__device__ __forceinline__ void mma_f16(float* d, uint32_t a0, uint32_t a1, uint32_t a2,
                                        uint32_t a3, uint32_t b0, uint32_t b1) {
    asm volatile(
        "mma.sync.aligned.m16n8k16.row.col.f32.f16.f16.f32 "
        "{%0,%1,%2,%3}, {%4,%5,%6,%7}, {%8,%9}, {%0,%1,%2,%3};"
        : "+f"(d[0]), "+f"(d[1]), "+f"(d[2]), "+f"(d[3])
        : "r"(a0), "r"(a1), "r"(a2), "r"(a3), "r"(b0), "r"(b1));
}

// ---------------- merged prepass (2 float4 per thread) ----------------
#define XBLKS (T_DIM * K_DIM / 8 / 256)     // 16384
#define WBLKS (N_DIM * K_DIM / 8 / 256)     // 8192

__global__ void __launch_bounds__(256)
convert_all_kernel(const float4* __restrict__ X4, const int4* __restrict__ W4)
{
    int b = blockIdx.x;
    if (b < XBLKS) {
        int i = b * 512 + threadIdx.x;
        #pragma unroll
        for (int e = 0; e < 2; e++, i += 256) {
            float4 v = X4[i];
            __half2 h0 = __floats2half2_rn(v.x, v.y);
            __half2 h1 = __floats2half2_rn(v.z, v.w);
            uint2 u;
            u.x = *reinterpret_cast<uint32_t*>(&h0);
            u.y = *reinterpret_cast<uint32_t*>(&h1);
            *reinterpret_cast<uint2*>(g_x + (size_t)i * 4) = u;
        }
    } else {
        int i = (b - XBLKS) * 512 + threadIdx.x;
        #pragma unroll
        for (int e = 0; e < 2; e++, i += 256) {
            int4 v = W4[i];
            __half2 h0 = __floats2half2_rn((float)v.x, (float)v.y);
            __half2 h1 = __floats2half2_rn((float)v.z, (float)v.w);
            uint2 u;
            u.x = *reinterpret_cast<uint32_t*>(&h0);
            u.y = *reinterpret_cast<uint32_t*>(&h1);
            *reinterpret_cast<uint2*>(g_w + (size_t)i * 4) = u;
        }
    }
}

// ---------------- main GEMM ----------------
__device__ __forceinline__ void fill_quarter_inc(uint32_t dstA, uint32_t dstB,
                                                 const __half* srcA,
                                                 const __half* srcB, int q) {
    cp16(dstA + (uint32_t)(q * DST_QSTRIDE), srcA + (size_t)q * QSTRIDE);
    cp16(dstB + (uint32_t)((q * 2 + 0) * DST_QSTRIDE), srcB + (size_t)(q * 2 + 0) * QSTRIDE);
    cp16(dstB + (uint32_t)((q * 2 + 1) * DST_QSTRIDE), srcB + (size_t)(q * 2 + 1) * QSTRIDE);
}

// load all 8 fragments (4 B + 4 A) of one ks-phase into buffers
__device__ __forceinline__ void load_phase(uint32_t base, const uint32_t* aoff,
                                           const uint32_t* boff, uint32_t kp,
                                           uint32_t bf[8][2], uint32_t af[4][4]) {
    #pragma unroll
    for (int nt = 0; nt < 4; nt++) {
        uint32_t r0, r1, r2, r3;
        ldm4(r0, r1, r2, r3, base + (boff[nt] ^ kp));
        bf[nt * 2 + 0][0] = r0; bf[nt * 2 + 0][1] = r2;
        bf[nt * 2 + 1][0] = r1; bf[nt * 2 + 1][1] = r3;
    }
    #pragma unroll
    for (int mt = 0; mt < 4; mt++)
        ldm4(af[mt][0], af[mt][1], af[mt][2], af[mt][3],
             base + (aoff[mt] ^ kp));
}

__global__ void __launch_bounds__(THREADS, 1)
qlinear_hmma_kernel(const float* __restrict__ scales,
                    const float* __restrict__ bias,
                    float* __restrict__ Out)
{
    extern __shared__ char smem[];
    const uint32_t sb = smem_u32(smem);
    const int tid = threadIdx.x;
    const int wid = tid >> 5;
    const int lane = tid & 31;

    const int n0 = blockIdx.x * BN;
    const int m0 = blockIdx.y * BM;

    const int wm = wid & 1;        // 2 warps over M
    const int wn = wid >> 1;       // 4 warps over N

    // per-thread fill bases (row = tid>>3, chunk = tid&7)
    const int fr = tid >> 3;
    const int fc = tid & 7;
    const uint32_t swz_t = SWZ((uint32_t)((fr << 7) + (fc << 4)));
    const __half* srcA = g_x + (size_t)(m0 + fr) * K_DIM + fc * 8;
    const __half* srcB = g_w + (size_t)(n0 + fr) * K_DIM + fc * 8;

    const int frow = lane & 15;
    const int fcol = lane >> 4;
    uint32_t aoff[4], boff[4];
    #pragma unroll
    for (int mt = 0; mt < 4; mt++) {
        uint32_t row = (uint32_t)(wm * 64 + mt * 16 + frow);
        aoff[mt] = A_B + ((row << 7) ^ ((row & 7) << 4));
    }
    #pragma unroll
    for (int nt = 0; nt < 4; nt++) {
        uint32_t row = (uint32_t)(wn * 64 + nt * 16 + frow);
        boff[nt] = B_B + ((row << 7) ^ ((row & 7) << 4));
    }
    const uint32_t kbase = (uint32_t)(fcol << 4);

    const int rot = (wid >> 2) * 2;    // SMSP de-phasing

    float acc[4][8][4];
    #pragma unroll
    for (int mt = 0; mt < 4; mt++)
        #pragma unroll
        for (int nf = 0; nf < 8; nf++)
            #pragma unroll
            for (int q = 0; q < 4; q++) acc[mt][nf][q] = 0.0f;

    // prologue: fill stages 0,1,2 with chunks 0,1,2
    #pragma unroll
    for (int s = 0; s < 3; s++) {
        const uint32_t dA = sb + s * STAGE_B + A_B + swz_t;
        const uint32_t dB = sb + s * STAGE_B + B_B + swz_t;
        #pragma unroll
        for (int q = 0; q < 4; q++)
            fill_quarter_inc(dA, dB, srcA + s * BK, srcB + s * BK, q);
        cp_commit();
    }
    srcA += 3 * BK;
    srcB += 3 * BK;

    int cons = 0, prod = 3;
    for (int c = 0; c < KITERS; c++) {
        cp_wait2();
        __syncthreads();

        const uint32_t base = sb + cons * STAGE_B;
        const bool do_fill = (c + 3 < KITERS);
        const uint32_t dA = sb + prod * STAGE_B + A_B + swz_t;
        const uint32_t dB = sb + prod * STAGE_B + B_B + swz_t;

        uint32_t bf[2][8][2];
        uint32_t af[2][4][4];

        // preload phase j=0 (ks = rot)
        load_phase(base, aoff, boff, kbase + (uint32_t)(rot * 32), bf[0], af[0]);

        #pragma unroll
        for (int j = 0; j < 4; j++) {
            const int cur = j & 1, nxt = cur ^ 1;

            if (do_fill)
                fill_quarter_inc(dA, dB, srcA, srcB, j);

            if (j < 3)
                load_phase(base, aoff, boff,
                           kbase + (uint32_t)((((j + 1 + rot) & 3)) * 32),
                           bf[nxt], af[nxt]);

            #pragma unroll
            for (int mt = 0; mt < 4; mt++)
                #pragma unroll
                for (int nf = 0; nf < 8; nf++)
                    mma_f16(acc[mt][nf],
                            af[cur][mt][0], af[cur][mt][1],
                            af[cur][mt][2], af[cur][mt][3],
                            bf[cur][nf][0], bf[cur][nf][1]);
        }
        cp_commit();
        srcA += BK;
        srcB += BK;

        cons = (cons == STAGES - 1) ? 0 : cons + 1;
        prod = (prod == STAGES - 1) ? 0 : prod + 1;
    }
    cp_wait0();

    // ---- epilogue ----
    #pragma unroll
    for (int mt = 0; mt < 4; mt++) {
        const int mrow = m0 + wm * 64 + mt * 16 + (lane >> 2);
        #pragma unroll
        for (int nf = 0; nf < 8; nf++) {
            const int n = n0 + wn * 64 + nf * 8 + (lane & 3) * 2;
            float2 sc = *reinterpret_cast<const float2*>(scales + n);
            float2 bi = *reinterpret_cast<const float2*>(bias + n);
            float2 o0, o1;
            o0.x = acc[mt][nf][0] * sc.x + bi.x;
            o0.y = acc[mt][nf][1] * sc.y + bi.y;
            o1.x = acc[mt][nf][2] * sc.x + bi.x;
            o1.y = acc[mt][nf][3] * sc.y + bi.y;
            *reinterpret_cast<float2*>(Out + (size_t)mrow * N_DIM + n) = o0;
            *reinterpret_cast<float2*>(Out + (size_t)(mrow + 8) * N_DIM + n) = o1;
        }
    }
}

// ---------------- host ----------------
extern "C" void kernel_launch(void* const* d_in, const int* in_sizes, int n_in,
                              void* d_out, int out_size)
{
    const float* x      = (const float*)d_in[0];
    const int*   w      = (const int*)d_in[1];
    const float* scales = (const float*)d_in[2];
    const float* bias   = (const float*)d_in[3];
    float* out = (float*)d_out;

    cudaFuncSetAttribute(qlinear_hmma_kernel,
                         cudaFuncAttributeMaxDynamicSharedMemorySize, SMEM_TOTAL);

    convert_all_kernel<<<XBLKS + WBLKS, 256>>>((const float4*)x, (const int4*)w);

    dim3 grid(N_DIM / BN, T_DIM / BM);   // 16 x 64
    qlinear_hmma_kernel<<<grid, THREADS, SMEM_TOTAL>>>(scales, bias, out);
}

// round 16
// speedup vs baseline: 1.2630x; 1.1564x over previous
#include <cuda_runtime.h>
#include <cuda_fp16.h>
#include <cstdint>

// out[T,N] = (x[T,K] @ W[N,K]^T) * scales[N] + bias[N];  T=8192, N=4096, K=4096
//
// R15: R14 base (fp16 HMMA, CTA 128x256, 8 warps 64x64, BK=64, 4-stage
// cp.async, incremental fill addressing, full fragment double-buffering,
// SMSP de-phasing) + CROSS-ITERATION fragment pipelining:
//   wait_group 1 guarantees chunk c+1 is complete at iter c, so the idle
//   j==3 prefetch slot loads next iter's phase-0 fragments from stage
//   cons+1. No exposed fragment preload after the per-iter sync.

#define T_DIM 8192
#define N_DIM 4096
#define K_DIM 4096

#define BM 128
#define BN 256
#define BK 64
#define STAGES 4
#define THREADS 256
#define KITERS (K_DIM / BK)      // 64

#define A_B 0
#define B_B 16384
#define STAGE_B 49152
#define SMEM_TOTAL (STAGES * STAGE_B)   // 196608

#define SWZ(o) ((o) ^ (((o) >> 3) & 0x70))

#define QSTRIDE (32 * K_DIM)            // 32 rows, in __half elements
#define DST_QSTRIDE 4096                // 32 rows * 128B

__device__ __align__(16) __half g_x[(size_t)T_DIM * K_DIM];
__device__ __align__(16) __half g_w[(size_t)N_DIM * K_DIM];

// ---------------- asm helpers ----------------
__device__ __forceinline__ uint32_t smem_u32(const void* p) {
    uint32_t a;
    asm("{ .reg .u64 t; cvta.to.shared.u64 t, %1; cvt.u32.u64 %0, t; }" : "=r"(a) : "l"(p));
    return a;
}
__device__ __forceinline__ void cp16(uint32_t dst, const void* src) {
    asm volatile("cp.async.cg.shared.global [%0], [%1], 16;" :: "r"(dst), "l"(src));
}
__device__ __forceinline__ void cp_commit() {
    asm volatile("cp.async.commit_group;" ::: "memory");
}
__device__ __forceinline__ void cp_wait2() {
    asm volatile("cp.async.wait_group 2;" ::: "memory");
}
__device__ __forceinline__ void cp_wait1() {
    asm volatile("cp.async.wait_group 1;" ::: "memory");
}
__device__ __forceinline__ void cp_wait0() {
    asm volatile("cp.async.wait_group 0;" ::: "memory");
}
__device__ __forceinline__ void ldm4(uint32_t& r0, uint32_t& r1, uint32_t& r2, uint32_t& r3,
                                     uint32_t addr) {
    asm volatile("ldmatrix.sync.aligned.m8n8.x4.shared.b16 {%0,%1,%2,%3}, [%4];"
                 : "=r"(r0), "=r"(r1), "=r"(r2), "=r"(r3) : "r"(addr));
}
__device__ __forceinline__ void mma_f16(float* d, uint32_t a0, uint32_t a1, uint32_t a2,
                                        uint32_t a3, uint32_t b0, uint32_t b1) {
    asm volatile(
        "mma.sync.aligned.m16n8k16.row.col.f32.f16.f16.f32 "
        "{%0,%1,%2,%3}, {%4,%5,%6,%7}, {%8,%9}, {%0,%1,%2,%3};"
        : "+f"(d[0]), "+f"(d[1]), "+f"(d[2]), "+f"(d[3])
        : "r"(a0), "r"(a1), "r"(a2), "r"(a3), "r"(b0), "r"(b1));
}

// ---------------- merged prepass (2 float4 per thread) ----------------
#define XBLKS (T_DIM * K_DIM / 8 / 256)     // 16384
#define WBLKS (N_DIM * K_DIM / 8 / 256)     // 8192

__global__ void __launch_bounds__(256)
convert_all_kernel(const float4* __restrict__ X4, const int4* __restrict__ W4)
{
    int b = blockIdx.x;
    if (b < XBLKS) {
        int i = b * 512 + threadIdx.x;
        #pragma unroll
        for (int e = 0; e < 2; e++, i += 256) {
            float4 v = X4[i];
            __half2 h0 = __floats2half2_rn(v.x, v.y);
            __half2 h1 = __floats2half2_rn(v.z, v.w);
            uint2 u;
            u.x = *reinterpret_cast<uint32_t*>(&h0);
            u.y = *reinterpret_cast<uint32_t*>(&h1);
            *reinterpret_cast<uint2*>(g_x + (size_t)i * 4) = u;
        }
    } else {
        int i = (b - XBLKS) * 512 + threadIdx.x;
        #pragma unroll
        for (int e = 0; e < 2; e++, i += 256) {
            int4 v = W4[i];
            __half2 h0 = __floats2half2_rn((float)v.x, (float)v.y);
            __half2 h1 = __floats2half2_rn((float)v.z, (float)v.w);
            uint2 u;
            u.x = *reinterpret_cast<uint32_t*>(&h0);
            u.y = *reinterpret_cast<uint32_t*>(&h1);
            *reinterpret_cast<uint2*>(g_w + (size_t)i * 4) = u;
        }
    }
}

// ---------------- main GEMM ----------------
__device__ __forceinline__ void fill_quarter_inc(uint32_t dstA, uint32_t dstB,
                                                 const __half* srcA,
                                                 const __half* srcB, int q) {
    cp16(dstA + (uint32_t)(q * DST_QSTRIDE), srcA + (size_t)q * QSTRIDE);
    cp16(dstB + (uint32_t)((q * 2 + 0) * DST_QSTRIDE), srcB + (size_t)(q * 2 + 0) * QSTRIDE);
    cp16(dstB + (uint32_t)((q * 2 + 1) * DST_QSTRIDE), srcB + (size_t)(q * 2 + 1) * QSTRIDE);
}

// load all 8 fragments (4 B + 4 A) of one ks-phase into buffers
__device__ __forceinline__ void load_phase(uint32_t base, const uint32_t* aoff,
                                           const uint32_t* boff, uint32_t kp,
                                           uint32_t bf[8][2], uint32_t af[4][4]) {
    #pragma unroll
    for (int nt = 0; nt < 4; nt++) {
        uint32_t r0, r1, r2, r3;
        ldm4(r0, r1, r2, r3, base + (boff[nt] ^ kp));
        bf[nt * 2 + 0][0] = r0; bf[nt * 2 + 0][1] = r2;
        bf[nt * 2 + 1][0] = r1; bf[nt * 2 + 1][1] = r3;
    }
    #pragma unroll
    for (int mt = 0; mt < 4; mt++)
        ldm4(af[mt][0], af[mt][1], af[mt][2], af[mt][3],
             base + (aoff[mt] ^ kp));
}

__global__ void __launch_bounds__(THREADS, 1)
qlinear_hmma_kernel(const float* __restrict__ scales,
                    const float* __restrict__ bias,
                    float* __restrict__ Out)
{
    extern __shared__ char smem[];
    const uint32_t sb = smem_u32(smem);
    const int tid = threadIdx.x;
    const int wid = tid >> 5;
    const int lane = tid & 31;

    const int n0 = blockIdx.x * BN;
    const int m0 = blockIdx.y * BM;

    const int wm = wid & 1;        // 2 warps over M
    const int wn = wid >> 1;       // 4 warps over N

    // per-thread fill bases (row = tid>>3, chunk = tid&7)
    const int fr = tid >> 3;
    const int fc = tid & 7;
    const uint32_t swz_t = SWZ((uint32_t)((fr << 7) + (fc << 4)));
    const __half* srcA = g_x + (size_t)(m0 + fr) * K_DIM + fc * 8;
    const __half* srcB = g_w + (size_t)(n0 + fr) * K_DIM + fc * 8;

    const int frow = lane & 15;
    const int fcol = lane >> 4;
    uint32_t aoff[4], boff[4];
    #pragma unroll
    for (int mt = 0; mt < 4; mt++) {
        uint32_t row = (uint32_t)(wm * 64 + mt * 16 + frow);
        aoff[mt] = A_B + ((row << 7) ^ ((row & 7) << 4));
    }
    #pragma unroll
    for (int nt = 0; nt < 4; nt++) {
        uint32_t row = (uint32_t)(wn * 64 + nt * 16 + frow);
        boff[nt] = B_B + ((row << 7) ^ ((row & 7) << 4));
    }
    const uint32_t kbase = (uint32_t)(fcol << 4);

    const int rot = (wid >> 2) * 2;    // SMSP de-phasing

    float acc[4][8][4];
    #pragma unroll
    for (int mt = 0; mt < 4; mt++)
        #pragma unroll
        for (int nf = 0; nf < 8; nf++)
            #pragma unroll
            for (int q = 0; q < 4; q++) acc[mt][nf][q] = 0.0f;

    // prologue: fill stages 0,1,2 with chunks 0,1,2
    #pragma unroll
    for (int s = 0; s < 3; s++) {
        const uint32_t dA = sb + s * STAGE_B + A_B + swz_t;
        const uint32_t dB = sb + s * STAGE_B + B_B + swz_t;
        #pragma unroll
        for (int q = 0; q < 4; q++)
            fill_quarter_inc(dA, dB, srcA + s * BK, srcB + s * BK, q);
        cp_commit();
    }
    srcA += 3 * BK;
    srcB += 3 * BK;

    uint32_t bf[2][8][2];
    uint32_t af[2][4][4];

    // initial preload: chunk 0, phase rot (chunk 0 complete after wait2)
    cp_wait2();
    __syncthreads();
    load_phase(sb, aoff, boff, kbase + (uint32_t)(rot * 32), bf[0], af[0]);

    int cons = 0, prod = 3;
    for (int c = 0; c < KITERS; c++) {
        cp_wait1();               // chunks <= c+1 complete
        __syncthreads();          // prod slot free + chunk c+1 visible

        const uint32_t base = sb + cons * STAGE_B;
        const uint32_t nbase = sb + (uint32_t)(((cons + 1) & 3) * STAGE_B);
        const bool do_fill = (c + 3 < KITERS);
        const uint32_t dA = sb + prod * STAGE_B + A_B + swz_t;
        const uint32_t dB = sb + prod * STAGE_B + B_B + swz_t;

        #pragma unroll
        for (int j = 0; j < 4; j++) {
            const int cur = j & 1, nxt = cur ^ 1;

            if (do_fill)
                fill_quarter_inc(dA, dB, srcA, srcB, j);

            // j<3: prefetch this chunk's next phase; j==3: prefetch NEXT
            // chunk's phase 0 ((j+1+rot)&3 == rot) from stage cons+1.
            load_phase(j < 3 ? base : nbase, aoff, boff,
                       kbase + (uint32_t)((((j + 1 + rot) & 3)) * 32),
                       bf[nxt], af[nxt]);

            #pragma unroll
            for (int mt = 0; mt < 4; mt++)
                #pragma unroll
                for (int nf = 0; nf < 8; nf++)
                    mma_f16(acc[mt][nf],
                            af[cur][mt][0], af[cur][mt][1],
                            af[cur][mt][2], af[cur][mt][3],
                            bf[cur][nf][0], bf[cur][nf][1]);
        }
        cp_commit();
        srcA += BK;
        srcB += BK;

        cons = (cons == STAGES - 1) ? 0 : cons + 1;
        prod = (prod == STAGES - 1) ? 0 : prod + 1;
    }
    cp_wait0();

    // ---- epilogue ----
    #pragma unroll
    for (int mt = 0; mt < 4; mt++) {
        const int mrow = m0 + wm * 64 + mt * 16 + (lane >> 2);
        #pragma unroll
        for (int nf = 0; nf < 8; nf++) {
            const int n = n0 + wn * 64 + nf * 8 + (lane & 3) * 2;
            float2 sc = *reinterpret_cast<const float2*>(scales + n);
            float2 bi = *reinterpret_cast<const float2*>(bias + n);
            float2 o0, o1;
            o0.x = acc[mt][nf][0] * sc.x + bi.x;
            o0.y = acc[mt][nf][1] * sc.y + bi.y;
            o1.x = acc[mt][nf][2] * sc.x + bi.x;
            o1.y = acc[mt][nf][3] * sc.y + bi.y;
            *reinterpret_cast<float2*>(Out + (size_t)mrow * N_DIM + n) = o0;
            *reinterpret_cast<float2*>(Out + (size_t)(mrow + 8) * N_DIM + n) = o1;
        }
    }
}

// ---------------- host ----------------
extern "C" void kernel_launch(void* const* d_in, const int* in_sizes, int n_in,
                              void* d_out, int out_size)
{
    const float* x      = (const float*)d_in[0];
    const int*   w      = (const int*)d_in[1];
    const float* scales = (const float*)d_in[2];
    const float* bias   = (const float*)d_in[3];
    float* out = (float*)d_out;

    cudaFuncSetAttribute(qlinear_hmma_kernel,
                         cudaFuncAttributeMaxDynamicSharedMemorySize, SMEM_TOTAL);

    convert_all_kernel<<<XBLKS + WBLKS, 256>>>((const float4*)x, (const int4*)w);

    dim3 grid(N_DIM / BN, T_DIM / BM);   // 16 x 64
    qlinear_hmma_kernel<<<grid, THREADS, SMEM_TOTAL>>>(scales, bias, out);
}